// round 4
// baseline (speedup 1.0000x reference)
#include <cuda_runtime.h>
#include <math.h>

// Block floating-point quantization (block_size=16, mantissa_bits=8).
// 4 consecutive lanes share one 16-elem block (one float4 each); every
// LDG.128 is fully warp-coalesced. Each thread handles 8 block-strided
// float4 chunks, all 8 loads issued before any dependent math (MLP_p1=8).

#define TPB 256
#define CHUNKS 8
#define TILE (TPB * CHUNKS)   // float4 per CTA = 2048

__device__ __forceinline__ float absmax4(float4 v) {
    return fmaxf(fmaxf(fabsf(v.x), fabsf(v.y)), fmaxf(fabsf(v.z), fabsf(v.w)));
}

__device__ __forceinline__ int bfp_exp(float a) {
    int ef = (__float_as_int(a) >> 23) & 0xFF;
    return (ef != 0) ? (ef - 127) : ((a > 0.0f) ? ilogbf(a) : 0);
}

__device__ __forceinline__ float4 bfp_quant(float4 v, int e) {
    int eb = e - 7;
    float s  = __int_as_float((eb + 127) << 23);
    float is = __int_as_float((127 - eb) << 23);
    float4 r;
    r.x = fminf(fmaxf(rintf(v.x * is), -128.0f), 127.0f) * s;
    r.y = fminf(fmaxf(rintf(v.y * is), -128.0f), 127.0f) * s;
    r.z = fminf(fmaxf(rintf(v.z * is), -128.0f), 127.0f) * s;
    r.w = fminf(fmaxf(rintf(v.w * is), -128.0f), 127.0f) * s;
    return r;
}

__global__ __launch_bounds__(TPB) void bfp_quant_kernel(
    const float4* __restrict__ in, float4* __restrict__ out, int n4)
{
    int base = blockIdx.x * TILE + threadIdx.x;

    if (base + (CHUNKS - 1) * TPB < n4) {
        // ---- full-tile fast path: no predicates, 8 front-batched loads ----
        float4 v[CHUNKS];
        #pragma unroll
        for (int c = 0; c < CHUNKS; c++) v[c] = __ldcs(in + base + c * TPB);

        float a[CHUNKS];
        #pragma unroll
        for (int c = 0; c < CHUNKS; c++) a[c] = absmax4(v[c]);
        #pragma unroll
        for (int c = 0; c < CHUNKS; c++) a[c] = fmaxf(a[c], __shfl_xor_sync(0xffffffffu, a[c], 1));
        #pragma unroll
        for (int c = 0; c < CHUNKS; c++) a[c] = fmaxf(a[c], __shfl_xor_sync(0xffffffffu, a[c], 2));

        #pragma unroll
        for (int c = 0; c < CHUNKS; c++) {
            float4 r = bfp_quant(v[c], bfp_exp(a[c]));
            __stcs(out + base + c * TPB, r);
        }
    } else {
        // ---- tail path (last CTA only) ----
        #pragma unroll
        for (int c = 0; c < CHUNKS; c++) {
            int i = base + c * TPB;
            if (i < n4) {
                float4 v = __ldcs(in + i);
                float a = absmax4(v);
                a = fmaxf(a, __shfl_xor_sync(0xffffffffu, a, 1));
                a = fmaxf(a, __shfl_xor_sync(0xffffffffu, a, 2));
                __stcs(out + i, bfp_quant(v, bfp_exp(a)));
            }
        }
    }
}

extern "C" void kernel_launch(void* const* d_in, const int* in_sizes, int n_in,
                              void* d_out, int out_size)
{
    const float4* x = (const float4*)d_in[0];
    float4* out = (float4*)d_out;
    int n = in_sizes[0];           // 4*4096*4096 = 67108864
    int n4 = n / 4;                // 16777216 float4
    int blocks = (n4 + TILE - 1) / TILE;   // 8192
    bfp_quant_kernel<<<blocks, TPB>>>(x, out, n4);
}

// round 5
// speedup vs baseline: 1.0016x; 1.0016x over previous
#include <cuda_runtime.h>
#include <math.h>

// Block floating-point quantization (block_size=16, mantissa_bits=8).
// 4 consecutive lanes share one 16-elem block (one float4 each); every
// LDG.128 is fully warp-coalesced. Each thread handles 6 block-strided
// float4 chunks, all 6 loads issued before any dependent math (MLP_p1=6).
// CHUNKS=6 balances per-thread MLP against occupancy (regs ~40 -> ~75% occ),
// maximizing per-SM loads in flight (warps x MLP).

#define TPB 256
#define CHUNKS 6
#define TILE (TPB * CHUNKS)   // float4 per CTA = 1536

__device__ __forceinline__ float absmax4(float4 v) {
    return fmaxf(fmaxf(fabsf(v.x), fabsf(v.y)), fmaxf(fabsf(v.z), fabsf(v.w)));
}

__device__ __forceinline__ int bfp_exp(float a) {
    int ef = (__float_as_int(a) >> 23) & 0xFF;
    return (ef != 0) ? (ef - 127) : ((a > 0.0f) ? ilogbf(a) : 0);
}

__device__ __forceinline__ float4 bfp_quant(float4 v, int e) {
    int eb = e - 7;
    float s  = __int_as_float((eb + 127) << 23);
    float is = __int_as_float((127 - eb) << 23);
    float4 r;
    r.x = fminf(fmaxf(rintf(v.x * is), -128.0f), 127.0f) * s;
    r.y = fminf(fmaxf(rintf(v.y * is), -128.0f), 127.0f) * s;
    r.z = fminf(fmaxf(rintf(v.z * is), -128.0f), 127.0f) * s;
    r.w = fminf(fmaxf(rintf(v.w * is), -128.0f), 127.0f) * s;
    return r;
}

__global__ __launch_bounds__(TPB) void bfp_quant_kernel(
    const float4* __restrict__ in, float4* __restrict__ out, int n4)
{
    int base = blockIdx.x * TILE + threadIdx.x;

    if (base + (CHUNKS - 1) * TPB < n4) {
        // ---- full-tile fast path: no predicates, 6 front-batched loads ----
        float4 v[CHUNKS];
        #pragma unroll
        for (int c = 0; c < CHUNKS; c++) v[c] = __ldcs(in + base + c * TPB);

        float a[CHUNKS];
        #pragma unroll
        for (int c = 0; c < CHUNKS; c++) a[c] = absmax4(v[c]);
        #pragma unroll
        for (int c = 0; c < CHUNKS; c++) a[c] = fmaxf(a[c], __shfl_xor_sync(0xffffffffu, a[c], 1));
        #pragma unroll
        for (int c = 0; c < CHUNKS; c++) a[c] = fmaxf(a[c], __shfl_xor_sync(0xffffffffu, a[c], 2));

        #pragma unroll
        for (int c = 0; c < CHUNKS; c++) {
            float4 r = bfp_quant(v[c], bfp_exp(a[c]));
            __stcs(out + base + c * TPB, r);
        }
    } else {
        // ---- tail path (last CTA only) ----
        #pragma unroll
        for (int c = 0; c < CHUNKS; c++) {
            int i = base + c * TPB;
            if (i < n4) {
                float4 v = __ldcs(in + i);
                float a = absmax4(v);
                a = fmaxf(a, __shfl_xor_sync(0xffffffffu, a, 1));
                a = fmaxf(a, __shfl_xor_sync(0xffffffffu, a, 2));
                __stcs(out + i, bfp_quant(v, bfp_exp(a)));
            }
        }
    }
}

extern "C" void kernel_launch(void* const* d_in, const int* in_sizes, int n_in,
                              void* d_out, int out_size)
{
    const float4* x = (const float4*)d_in[0];
    float4* out = (float4*)d_out;
    int n = in_sizes[0];           // 4*4096*4096 = 67108864
    int n4 = n / 4;                // 16777216 float4
    int blocks = (n4 + TILE - 1) / TILE;   // 10923
    bfp_quant_kernel<<<blocks, TPB>>>(x, out, n4);
}